// round 1
// baseline (speedup 1.0000x reference)
#include <cuda_runtime.h>
#include <math.h>

// Problem constants
#define BB   16
#define NN_  1024
#define CC   256
#define BNC  (BB * NN_ * CC)      // 4,194,304
#define BNN  (BB * NN_ * NN_)     // 16,777,216
#define NC   (NN_ * CC)           // 262,144
#define N2   (NN_ * NN_)          // 1,048,576

// Scratch (allocation-free: __device__ globals)
__device__ float g_Q[BNC];
__device__ float g_K[BNC];
__device__ float g_V[BNC];
__device__ float g_sig[BB * NN_];

// ---------------------------------------------------------------------------
// Generic tiled SGEMM: C = alpha * A @ B   (or A @ B^T when TRANSB)
// A: [M,K] row-major. B: [K,N] row-major (NN) or [N,K] row-major (NT).
// Tile: 64x64x16, 256 threads, 4x4 per-thread microtile.
// All dims are multiples of 64/16 for this problem -> no bounds checks.
// Batched via blockIdx.z with element strides sA/sB/sC.
// ---------------------------------------------------------------------------
template<bool TRANSB>
__global__ __launch_bounds__(256) void sgemm(
    const float* __restrict__ A, const float* __restrict__ Bm,
    float* __restrict__ C, int M, int N, int K,
    size_t sA, size_t sB, size_t sC, float alpha)
{
    __shared__ float As[16][64];
    __shared__ float Bs[16][64];

    A  += (size_t)blockIdx.z * sA;
    Bm += (size_t)blockIdx.z * sB;
    C  += (size_t)blockIdx.z * sC;

    const int t  = threadIdx.x;
    const int tx = t & 15;
    const int ty = t >> 4;
    const int m0 = blockIdx.y * 64;
    const int n0 = blockIdx.x * 64;

    const int ar = t >> 2;          // 0..63
    const int ac = (t & 3) * 4;     // 0,4,8,12

    float acc[4][4] = {};

    for (int k0 = 0; k0 < K; k0 += 16) {
        // A tile: rows m0+ar, cols k0+ac..+3 -> As[k][m] (transposed)
        float4 av = *(const float4*)(A + (size_t)(m0 + ar) * K + (k0 + ac));
        As[ac + 0][ar] = av.x;
        As[ac + 1][ar] = av.y;
        As[ac + 2][ar] = av.z;
        As[ac + 3][ar] = av.w;

        if (TRANSB) {
            // B^T: logical B[k][n] = Bm[n][k];  Bm is [N,K] row-major
            float4 bv = *(const float4*)(Bm + (size_t)(n0 + ar) * K + (k0 + ac));
            Bs[ac + 0][ar] = bv.x;
            Bs[ac + 1][ar] = bv.y;
            Bs[ac + 2][ar] = bv.z;
            Bs[ac + 3][ar] = bv.w;
        } else {
            const int br = t >> 4;          // 0..15
            const int bc = (t & 15) * 4;    // 0..60
            float4 bv = *(const float4*)(Bm + (size_t)(k0 + br) * N + (n0 + bc));
            *(float4*)&Bs[br][bc] = bv;
        }
        __syncthreads();

        #pragma unroll
        for (int k = 0; k < 16; k++) {
            float a[4], b[4];
            #pragma unroll
            for (int i = 0; i < 4; i++) a[i] = As[k][ty * 4 + i];
            #pragma unroll
            for (int j = 0; j < 4; j++) b[j] = Bs[k][tx * 4 + j];
            #pragma unroll
            for (int i = 0; i < 4; i++)
                #pragma unroll
                for (int j = 0; j < 4; j++)
                    acc[i][j] += a[i] * b[j];
        }
        __syncthreads();
    }

    #pragma unroll
    for (int i = 0; i < 4; i++) {
        #pragma unroll
        for (int j = 0; j < 4; j++)
            C[(size_t)(m0 + ty * 4 + i) * N + (n0 + tx * 4 + j)] = alpha * acc[i][j];
    }
}

// ---------------------------------------------------------------------------
// sigma = |x @ W_sigma|   one warp per row (row = b*N + i), 256-length dot
// ---------------------------------------------------------------------------
__global__ void sigma_kernel(const float* __restrict__ x,
                             const float* __restrict__ Wsig,
                             float* __restrict__ out)
{
    int gwarp = (blockIdx.x * blockDim.x + threadIdx.x) >> 5;
    int lane  = threadIdx.x & 31;
    if (gwarp >= BB * NN_) return;
    const float* xr = x + (size_t)gwarp * CC;
    float s = 0.f;
    #pragma unroll
    for (int c = lane; c < CC; c += 32) s += xr[c] * Wsig[c];
    #pragma unroll
    for (int o = 16; o > 0; o >>= 1) s += __shfl_down_sync(0xFFFFFFFFu, s, o);
    if (lane == 0) out[gwarp] = fabsf(s);
}

// ---------------------------------------------------------------------------
// softmax over the BATCH axis, in place on S [B, N, N]
// each thread handles one (n,m), reading 16 values at stride N*N
// ---------------------------------------------------------------------------
__global__ void softmax_batch(float* __restrict__ S)
{
    size_t idx = (size_t)blockIdx.x * blockDim.x + threadIdx.x;  // < N*N
    float v[BB];
    float m = -3.0e38f;
    #pragma unroll
    for (int b = 0; b < BB; b++) {
        v[b] = S[(size_t)b * N2 + idx];
        m = fmaxf(m, v[b]);
    }
    float s = 0.f;
    #pragma unroll
    for (int b = 0; b < BB; b++) {
        v[b] = __expf(v[b] - m);
        s += v[b];
    }
    float inv = 1.0f / s;
    #pragma unroll
    for (int b = 0; b < BB; b++)
        S[(size_t)b * N2 + idx] = v[b] * inv;
}

// ---------------------------------------------------------------------------
// P[b,i,j] = (|i-j| + |sigma[b,i]| * eps[b,i,j]) / row_sum
// one block (256 threads) per row; gaussian kept in registers
// ---------------------------------------------------------------------------
__global__ __launch_bounds__(256) void p_kernel(const float* __restrict__ eps,
                                                const float* __restrict__ sig,
                                                float* __restrict__ P)
{
    int row = blockIdx.x;            // b*N + i
    int i   = row & (NN_ - 1);
    float sg = sig[row];
    const float* e = eps + (size_t)row * NN_;
    float* p = P + (size_t)row * NN_;

    float g[4];
    float partial = 0.f;
    #pragma unroll
    for (int k = 0; k < 4; k++) {
        int j = threadIdx.x + k * 256;
        g[k] = fabsf((float)(i - j)) + sg * e[j];
        partial += g[k];
    }

    __shared__ float red[256];
    red[threadIdx.x] = partial;
    __syncthreads();
    #pragma unroll
    for (int o = 128; o > 0; o >>= 1) {
        if (threadIdx.x < o) red[threadIdx.x] += red[threadIdx.x + o];
        __syncthreads();
    }
    float inv = 1.0f / red[0];
    #pragma unroll
    for (int k = 0; k < 4; k++)
        p[threadIdx.x + k * 256] = g[k] * inv;
}

// ---------------------------------------------------------------------------
extern "C" void kernel_launch(void* const* d_in, const int* in_sizes, int n_in,
                              void* d_out, int out_size)
{
    const float* x      = (const float*)d_in[0];   // [16,1024,256]
    const float* W_q    = (const float*)d_in[1];   // [256,256]
    const float* W_k    = (const float*)d_in[2];   // [256,256]
    const float* W_v    = (const float*)d_in[3];   // [256,256]
    const float* W_sig  = (const float*)d_in[4];   // [256,1]
    const float* eps    = (const float*)d_in[5];   // [16,1024,1024]

    float* out = (float*)d_out;
    float* Z = out;                   // [16,1024,256]
    float* P = out + BNC;             // [16,1024,1024]
    float* S = out + BNC + BNN;       // [16,1024,1024]

    void *pq, *pk, *pv, *psig;
    cudaGetSymbolAddress(&pq,   g_Q);
    cudaGetSymbolAddress(&pk,   g_K);
    cudaGetSymbolAddress(&pv,   g_V);
    cudaGetSymbolAddress(&psig, g_sig);
    float* Q  = (float*)pq;
    float* Kb = (float*)pk;
    float* V  = (float*)pv;
    float* sg = (float*)psig;

    const int M_qkv = BB * NN_;   // 16384

    // --- projections: Q/K/V = x @ W  (M=16384, N=256, K=256) ---
    {
        dim3 grid(CC / 64, M_qkv / 64, 1);
        sgemm<false><<<grid, 256>>>(x, W_q, Q,  M_qkv, CC, CC, 0, 0, 0, 1.0f);
        sgemm<false><<<grid, 256>>>(x, W_k, Kb, M_qkv, CC, CC, 0, 0, 0, 1.0f);
        sgemm<false><<<grid, 256>>>(x, W_v, V,  M_qkv, CC, CC, 0, 0, 0, 1.0f);
    }

    // --- sigma = |x @ W_sigma| ---
    sigma_kernel<<<(M_qkv * 32 + 127) / 128, 128>>>(x, W_sig, sg);

    // --- scores = (Q @ K^T) / 16 written straight into the S output region ---
    {
        dim3 grid(NN_ / 64, NN_ / 64, BB);
        sgemm<true><<<grid, 256>>>(Q, Kb, S, NN_, NN_, CC,
                                   (size_t)NC, (size_t)NC, (size_t)N2, 0.0625f);
    }

    // --- softmax over batch axis, in place ---
    softmax_batch<<<N2 / 256, 256>>>(S);

    // --- P (prior association), independent of scores path ---
    p_kernel<<<BB * NN_, 256>>>(eps, sg, P);

    // --- Z = S @ V ---
    {
        dim3 grid(CC / 64, NN_ / 64, BB);
        sgemm<false><<<grid, 256>>>(S, V, Z, NN_, CC, NN_,
                                    (size_t)N2, (size_t)NC, (size_t)NC, 1.0f);
    }
}

// round 5
// speedup vs baseline: 2.4078x; 2.4078x over previous
#include <cuda_runtime.h>
#include <cuda_bf16.h>
#include <cstdint>
#include <math.h>

#define BB   16
#define NN_  1024
#define CC   256
#define BNC  (BB * NN_ * CC)      // 4,194,304
#define BNN  (BB * NN_ * NN_)     // 16,777,216
#define NC   (NN_ * CC)           // 262,144
#define N2   (NN_ * NN_)          // 1,048,576

typedef __nv_bfloat16 bf16;

// ---------------- scratch (__device__ globals: allocation-free) -------------
__device__ __align__(16) bf16 g_xhi[BNC],  g_xlo[BNC];
__device__ __align__(16) bf16 g_Whi[3][CC * CC], g_Wlo[3][CC * CC];
__device__ __align__(16) bf16 g_Qhi[BNC],  g_Qlo[BNC];
__device__ __align__(16) bf16 g_Khi[BNC],  g_Klo[BNC];
__device__ __align__(16) bf16 g_Vhi[BNC],  g_Vlo[BNC];
__device__ __align__(16) bf16 g_Shi[BNN],  g_Slo[BNN];
__device__ float g_sig[BB * NN_];

// ---------------- base-target PTX helpers (no 'a' features!) ----------------
__device__ __forceinline__ uint32_t smem_u32(const void* p) {
    uint32_t a;
    asm("{ .reg .u64 t; cvta.to.shared.u64 t, %1; cvt.u32.u64 %0, t; }" : "=r"(a) : "l"(p));
    return a;
}
__device__ __forceinline__ void cpa16(uint32_t s, const void* g) {
    asm volatile("cp.async.cg.shared.global [%0], [%1], 16;" :: "r"(s), "l"(g));
}
#define CP_COMMIT() asm volatile("cp.async.commit_group;" ::: "memory")
#define CP_WAIT0()  asm volatile("cp.async.wait_group 0;"  ::: "memory")

__device__ __forceinline__ void mma16816(float* d, const uint32_t* a, const uint32_t* b) {
    asm volatile(
        "mma.sync.aligned.m16n8k16.row.col.f32.bf16.bf16.f32 "
        "{%0,%1,%2,%3}, {%4,%5,%6,%7}, {%8,%9}, {%0,%1,%2,%3};"
        : "+f"(d[0]), "+f"(d[1]), "+f"(d[2]), "+f"(d[3])
        : "r"(a[0]), "r"(a[1]), "r"(a[2]), "r"(a[3]), "r"(b[0]), "r"(b[1]));
}

// ---------------- smem tile geometry ----------------------------------------
// A / B-NT tiles: 128 rows x 32 bf16 (64B rows), swizzle: unit c(0..3) ^= (r>>1)&3
// B-NN tile:      32 rows x 128 bf16 (256B rows), swizzle: unit c(0..15) ^= r&7
#define OFF_AH 0u
#define OFF_AL 8192u
#define OFF_BH 16384u
#define OFF_BL 24576u
#define STAGE  32768u
#define SMEM_DYN (2 * STAGE)

__device__ __forceinline__ uint32_t swzA(int r, int c) {
    return (uint32_t)(r * 64 + ((c ^ ((r >> 1) & 3)) << 4));
}
__device__ __forceinline__ uint32_t swzB(int r, int c) {
    return (uint32_t)(r * 256 + ((c ^ (r & 7)) << 4));
}

template<bool NT>
__device__ __forceinline__ void load_stage(
    uint32_t sb, const bf16* __restrict__ Ah, const bf16* __restrict__ Al,
    const bf16* __restrict__ Bh, const bf16* __restrict__ Bl,
    int ldA, int ldB, int m0, int n0, int k0, int t)
{
    #pragma unroll
    for (int i = 0; i < 2; i++) {
        int u = t + (i << 8);
        int r = u >> 2, c = u & 3;
        uint32_t so = swzA(r, c);
        size_t go = (size_t)(m0 + r) * ldA + k0 + c * 8;
        cpa16(sb + OFF_AH + so, Ah + go);
        cpa16(sb + OFF_AL + so, Al + go);
    }
    if (NT) {
        #pragma unroll
        for (int i = 0; i < 2; i++) {
            int u = t + (i << 8);
            int r = u >> 2, c = u & 3;
            uint32_t so = swzA(r, c);
            size_t go = (size_t)(n0 + r) * ldB + k0 + c * 8;
            cpa16(sb + OFF_BH + so, Bh + go);
            cpa16(sb + OFF_BL + so, Bl + go);
        }
    } else {
        #pragma unroll
        for (int i = 0; i < 2; i++) {
            int u = t + (i << 8);
            int r = u >> 4, c = u & 15;
            uint32_t so = swzB(r, c);
            size_t go = (size_t)(k0 + r) * ldB + n0 + c * 8;
            cpa16(sb + OFF_BH + so, Bh + go);
            cpa16(sb + OFF_BL + so, Bl + go);
        }
    }
}

__device__ __forceinline__ void lds_a(uint32_t base, int wm, int lane, uint32_t af[2][4][4]) {
    #pragma unroll
    for (int k2 = 0; k2 < 2; k2++)
        #pragma unroll
        for (int mi = 0; mi < 4; mi++) {
            int row = wm * 64 + mi * 16 + (lane & 15);
            int c   = k2 * 2 + (lane >> 4);
            uint32_t a = base + swzA(row, c);
            asm volatile("ldmatrix.sync.aligned.m8n8.x4.shared.b16 {%0,%1,%2,%3}, [%4];"
                : "=r"(af[k2][mi][0]), "=r"(af[k2][mi][1]),
                  "=r"(af[k2][mi][2]), "=r"(af[k2][mi][3]) : "r"(a));
        }
}

template<bool NT>
__device__ __forceinline__ void lds_b(uint32_t base, int wn, int lane, uint32_t bfr[2][4][2]) {
    #pragma unroll
    for (int k2 = 0; k2 < 2; k2++)
        #pragma unroll
        for (int nb = 0; nb < 4; nb++) {
            if (NT) {
                int row = wn * 32 + nb * 8 + (lane & 7);
                int c   = k2 * 2 + ((lane >> 3) & 1);
                uint32_t a = base + swzA(row, c);
                asm volatile("ldmatrix.sync.aligned.m8n8.x2.shared.b16 {%0,%1}, [%2];"
                    : "=r"(bfr[k2][nb][0]), "=r"(bfr[k2][nb][1]) : "r"(a));
            } else {
                int row = k2 * 16 + (lane & 15);
                int c   = wn * 4 + nb;
                uint32_t a = base + swzB(row, c);
                asm volatile("ldmatrix.sync.aligned.m8n8.x2.trans.shared.b16 {%0,%1}, [%2];"
                    : "=r"(bfr[k2][nb][0]), "=r"(bfr[k2][nb][1]) : "r"(a));
            }
        }
}

// ---------------------------------------------------------------------------
// Split-bf16 HMMA GEMM:  D[m][n] = alpha * sum_k A[m][k] * B'[k][n]
//   NT=true : B given as [N][K] row-major (B' = given^T)
//   NT=false: B given as [K][N] row-major
//   MODE 0: fp32*alpha out.  MODE 1: bf16 hi/lo out.
// CTA: 128x128 tile, 8 warps (2x4), warp tile 64x32, K-chunk 32, 2-stage pipe.
// ---------------------------------------------------------------------------
template<bool NT, int MODE>
__global__ __launch_bounds__(256, 1) void gemm_mma(
    const bf16* __restrict__ Ah, const bf16* __restrict__ Al,
    const bf16* __restrict__ Bh, const bf16* __restrict__ Bl,
    float* __restrict__ Cf, bf16* __restrict__ Ch, bf16* __restrict__ Cl,
    int ldA, int ldB, int ldC, int K,
    size_t sA_, size_t sB_, size_t sC_, float alpha)
{
    extern __shared__ char sm[];
    uint32_t sb = smem_u32(sm);

    const int t    = threadIdx.x;
    const int warp = t >> 5;
    const int lane = t & 31;
    const int wm   = warp >> 2;   // 0..1
    const int wn   = warp & 3;    // 0..3

    const size_t z = blockIdx.z;
    Ah += z * sA_; Al += z * sA_; Bh += z * sB_; Bl += z * sB_;
    const int m0 = blockIdx.y * 128;
    const int n0 = blockIdx.x * 128;

    float acc[4][4][4] = {};
    const int nk = K >> 5;

    load_stage<NT>(sb, Ah, Al, Bh, Bl, ldA, ldB, m0, n0, 0, t);
    CP_COMMIT();

    uint32_t af[2][4][4];
    uint32_t bfr[2][4][2];

    for (int c = 0; c < nk; c++) {
        CP_WAIT0();
        __syncthreads();
        if (c + 1 < nk) {
            load_stage<NT>(sb + ((c + 1) & 1) * STAGE, Ah, Al, Bh, Bl,
                           ldA, ldB, m0, n0, (c + 1) << 5, t);
            CP_COMMIT();
        }
        uint32_t st = sb + (c & 1) * STAGE;

        // pass 1: Ah * Bh
        lds_a(st + OFF_AH, wm, lane, af);
        lds_b<NT>(st + OFF_BH, wn, lane, bfr);
        #pragma unroll
        for (int k2 = 0; k2 < 2; k2++)
            #pragma unroll
            for (int mi = 0; mi < 4; mi++)
                #pragma unroll
                for (int ni = 0; ni < 4; ni++)
                    mma16816(acc[mi][ni], af[k2][mi], bfr[k2][ni]);

        // pass 2: Ah * Bl (reuse A frags)
        lds_b<NT>(st + OFF_BL, wn, lane, bfr);
        #pragma unroll
        for (int k2 = 0; k2 < 2; k2++)
            #pragma unroll
            for (int mi = 0; mi < 4; mi++)
                #pragma unroll
                for (int ni = 0; ni < 4; ni++)
                    mma16816(acc[mi][ni], af[k2][mi], bfr[k2][ni]);

        // pass 3: Al * Bh
        lds_a(st + OFF_AL, wm, lane, af);
        lds_b<NT>(st + OFF_BH, wn, lane, bfr);
        #pragma unroll
        for (int k2 = 0; k2 < 2; k2++)
            #pragma unroll
            for (int mi = 0; mi < 4; mi++)
                #pragma unroll
                for (int ni = 0; ni < 4; ni++)
                    mma16816(acc[mi][ni], af[k2][mi], bfr[k2][ni]);
    }

    // ---- epilogue: fragments are (row, 2-col pairs) -> direct stores ----
    const int g   = lane >> 2;
    const int tig = lane & 3;
    #pragma unroll
    for (int mi = 0; mi < 4; mi++) {
        #pragma unroll
        for (int ni = 0; ni < 4; ni++) {
            int row = m0 + wm * 64 + mi * 16 + g;
            int col = n0 + wn * 32 + ni * 8 + tig * 2;
            if (MODE == 0) {
                float* C = Cf + z * sC_;
                float2 v0 = make_float2(acc[mi][ni][0] * alpha, acc[mi][ni][1] * alpha);
                float2 v1 = make_float2(acc[mi][ni][2] * alpha, acc[mi][ni][3] * alpha);
                *(float2*)&C[(size_t)row * ldC + col]       = v0;
                *(float2*)&C[(size_t)(row + 8) * ldC + col] = v1;
            } else {
                bf16* H = Ch + z * sC_;
                bf16* L = Cl + z * sC_;
                #pragma unroll
                for (int rr = 0; rr < 2; rr++) {
                    float v0 = acc[mi][ni][rr * 2 + 0];
                    float v1 = acc[mi][ni][rr * 2 + 1];
                    bf16 h0 = __float2bfloat16(v0);
                    bf16 h1 = __float2bfloat16(v1);
                    bf16 l0 = __float2bfloat16(v0 - __bfloat162float(h0));
                    bf16 l1 = __float2bfloat16(v1 - __bfloat162float(h1));
                    size_t o = (size_t)(row + rr * 8) * ldC + col;
                    *(__nv_bfloat162*)&H[o] = __nv_bfloat162(h0, h1);
                    *(__nv_bfloat162*)&L[o] = __nv_bfloat162(l0, l1);
                }
            }
        }
    }
}

// ---------------------------------------------------------------------------
// elementwise fp32 -> bf16 hi/lo split
// ---------------------------------------------------------------------------
__global__ void split_kernel(const float* __restrict__ src,
                             bf16* __restrict__ hi, bf16* __restrict__ lo, int n)
{
    int i = blockIdx.x * blockDim.x + threadIdx.x;
    if (i >= n) return;
    float v = src[i];
    bf16 h = __float2bfloat16(v);
    hi[i] = h;
    lo[i] = __float2bfloat16(v - __bfloat162float(h));
}

// ---------------------------------------------------------------------------
// sigma = |x @ W_sigma|  (fp32, exact)
// ---------------------------------------------------------------------------
__global__ void sigma_kernel(const float* __restrict__ x,
                             const float* __restrict__ Wsig,
                             float* __restrict__ out)
{
    int gwarp = (blockIdx.x * blockDim.x + threadIdx.x) >> 5;
    int lane  = threadIdx.x & 31;
    if (gwarp >= BB * NN_) return;
    const float* xr = x + (size_t)gwarp * CC;
    float s = 0.f;
    #pragma unroll
    for (int c = lane; c < CC; c += 32) s += xr[c] * Wsig[c];
    #pragma unroll
    for (int o = 16; o > 0; o >>= 1) s += __shfl_down_sync(0xFFFFFFFFu, s, o);
    if (lane == 0) out[gwarp] = fabsf(s);
}

// ---------------------------------------------------------------------------
// batch softmax in place on S (fp32), plus bf16 hi/lo copies for SV GEMM
// ---------------------------------------------------------------------------
__global__ void softmax_batch_split(float* __restrict__ S,
                                    bf16* __restrict__ Shi, bf16* __restrict__ Slo)
{
    size_t idx = (size_t)blockIdx.x * blockDim.x + threadIdx.x;  // < N*N
    float v[BB];
    float m = -3.0e38f;
    #pragma unroll
    for (int b = 0; b < BB; b++) {
        v[b] = S[(size_t)b * N2 + idx];
        m = fmaxf(m, v[b]);
    }
    float s = 0.f;
    #pragma unroll
    for (int b = 0; b < BB; b++) { v[b] = __expf(v[b] - m); s += v[b]; }
    float inv = 1.0f / s;
    #pragma unroll
    for (int b = 0; b < BB; b++) {
        float w = v[b] * inv;
        size_t o = (size_t)b * N2 + idx;
        S[o] = w;
        bf16 h = __float2bfloat16(w);
        Shi[o] = h;
        Slo[o] = __float2bfloat16(w - __bfloat162float(h));
    }
}

// ---------------------------------------------------------------------------
// P[b,i,j] = (|i-j| + sigma[b,i] * eps[b,i,j]) / row_sum
// ---------------------------------------------------------------------------
__global__ __launch_bounds__(256) void p_kernel(const float* __restrict__ eps,
                                                const float* __restrict__ sig,
                                                float* __restrict__ P)
{
    int row = blockIdx.x;
    int i   = row & (NN_ - 1);
    float sg = sig[row];
    const float* e = eps + (size_t)row * NN_;
    float* p = P + (size_t)row * NN_;

    float gv[4];
    float partial = 0.f;
    #pragma unroll
    for (int k = 0; k < 4; k++) {
        int j = threadIdx.x + k * 256;
        gv[k] = fabsf((float)(i - j)) + sg * e[j];
        partial += gv[k];
    }
    __shared__ float red[256];
    red[threadIdx.x] = partial;
    __syncthreads();
    #pragma unroll
    for (int o = 128; o > 0; o >>= 1) {
        if (threadIdx.x < o) red[threadIdx.x] += red[threadIdx.x + o];
        __syncthreads();
    }
    float inv = 1.0f / red[0];
    #pragma unroll
    for (int k = 0; k < 4; k++)
        p[threadIdx.x + k * 256] = gv[k] * inv;
}

// ---------------------------------------------------------------------------
extern "C" void kernel_launch(void* const* d_in, const int* in_sizes, int n_in,
                              void* d_out, int out_size)
{
    const float* x     = (const float*)d_in[0];
    const float* W_q   = (const float*)d_in[1];
    const float* W_k   = (const float*)d_in[2];
    const float* W_v   = (const float*)d_in[3];
    const float* W_sig = (const float*)d_in[4];
    const float* eps   = (const float*)d_in[5];

    float* out = (float*)d_out;
    float* Z = out;
    float* P = out + BNC;
    float* S = out + BNC + BNN;

    #define SYM(T, v, s) T* v; { void* _p; cudaGetSymbolAddress(&_p, s); v = (T*)_p; }
    SYM(bf16, xhi, g_xhi)   SYM(bf16, xlo, g_xlo)
    SYM(bf16, Whi, g_Whi)   SYM(bf16, Wlo, g_Wlo)
    SYM(bf16, Qhi, g_Qhi)   SYM(bf16, Qlo, g_Qlo)
    SYM(bf16, Khi, g_Khi)   SYM(bf16, Klo, g_Klo)
    SYM(bf16, Vhi, g_Vhi)   SYM(bf16, Vlo, g_Vlo)
    SYM(bf16, Shi, g_Shi)   SYM(bf16, Slo, g_Slo)
    SYM(float, sg, g_sig)
    #undef SYM

    cudaFuncSetAttribute(gemm_mma<false, 1>, cudaFuncAttributeMaxDynamicSharedMemorySize, SMEM_DYN);
    cudaFuncSetAttribute(gemm_mma<true,  0>, cudaFuncAttributeMaxDynamicSharedMemorySize, SMEM_DYN);
    cudaFuncSetAttribute(gemm_mma<false, 0>, cudaFuncAttributeMaxDynamicSharedMemorySize, SMEM_DYN);

    // 1) split inputs to bf16 hi/lo (no transposes needed)
    split_kernel<<<(BNC + 255) / 256, 256>>>(x, xhi, xlo, BNC);
    split_kernel<<<CC * CC / 256, 256>>>(W_q, Whi + 0 * CC * CC, Wlo + 0 * CC * CC, CC * CC);
    split_kernel<<<CC * CC / 256, 256>>>(W_k, Whi + 1 * CC * CC, Wlo + 1 * CC * CC, CC * CC);
    split_kernel<<<CC * CC / 256, 256>>>(W_v, Whi + 2 * CC * CC, Wlo + 2 * CC * CC, CC * CC);

    // 2) projections: Q/K/V = x @ W  (B is [K][N] -> NN form), bf16 hi/lo out
    {
        dim3 grid(CC / 128, (BB * NN_) / 128, 1);
        gemm_mma<false, 1><<<grid, 256, SMEM_DYN>>>(
            xhi, xlo, Whi + 0 * CC * CC, Wlo + 0 * CC * CC,
            nullptr, Qhi, Qlo, CC, CC, CC, CC, 0, 0, 0, 1.f);
        gemm_mma<false, 1><<<grid, 256, SMEM_DYN>>>(
            xhi, xlo, Whi + 1 * CC * CC, Wlo + 1 * CC * CC,
            nullptr, Khi, Klo, CC, CC, CC, CC, 0, 0, 0, 1.f);
        gemm_mma<false, 1><<<grid, 256, SMEM_DYN>>>(
            xhi, xlo, Whi + 2 * CC * CC, Wlo + 2 * CC * CC,
            nullptr, Vhi, Vlo, CC, CC, CC, CC, 0, 0, 0, 1.f);
    }

    // 3) sigma (fp32 exact)
    sigma_kernel<<<(BB * NN_ * 32 + 127) / 128, 128>>>(x, W_sig, sg);

    // 4) scores = Q K^T / 16 into S region (K is [N][K] -> NT form)
    {
        dim3 grid(NN_ / 128, NN_ / 128, BB);
        gemm_mma<true, 0><<<grid, 256, SMEM_DYN>>>(
            Qhi, Qlo, Khi, Klo, S, nullptr, nullptr,
            CC, CC, NN_, CC, (size_t)NC, (size_t)NC, (size_t)N2, 0.0625f);
    }

    // 5) batch softmax in place + bf16 split of S
    softmax_batch_split<<<N2 / 256, 256>>>(S, Shi, Slo);

    // 6) prior association P
    p_kernel<<<BB * NN_, 256>>>(eps, sg, P);

    // 7) Z = S @ V  (V is [K][N] -> NN form)
    {
        dim3 grid(CC / 128, NN_ / 128, BB);
        gemm_mma<false, 0><<<grid, 256, SMEM_DYN>>>(
            Shi, Slo, Vhi, Vlo, Z, nullptr, nullptr,
            NN_, CC, CC, NN_, (size_t)N2, (size_t)NC, (size_t)NC, 1.f);
    }
}

// round 8
// speedup vs baseline: 3.2493x; 1.3495x over previous
#include <cuda_runtime.h>
#include <cuda_fp16.h>
#include <cstdint>
#include <math.h>

#define BB   16
#define NN_  1024
#define CC   256
#define BNC  (BB * NN_ * CC)      // 4,194,304
#define BNN  (BB * NN_ * NN_)     // 16,777,216
#define NC   (NN_ * CC)           // 262,144
#define N2   (NN_ * NN_)          // 1,048,576

// ---------------- scratch (__device__ globals: allocation-free) -------------
__device__ __align__(16) __half g_xh[BNC], g_xl[BNC];
__device__ __align__(16) __half g_W[3][CC * CC];
__device__ __align__(16) __half g_Qh[BNC], g_Ql[BNC];
__device__ __align__(16) __half g_Kh[BNC];
__device__ __align__(16) __half g_Vh[BNC];
__device__ __align__(16) __half g_Sh[BNN], g_Sl[BNN];
__device__ float g_sig[BB * NN_];

// ---------------- base-target PTX helpers -----------------------------------
__device__ __forceinline__ uint32_t smem_u32(const void* p) {
    uint32_t a;
    asm("{ .reg .u64 t; cvta.to.shared.u64 t, %1; cvt.u32.u64 %0, t; }" : "=r"(a) : "l"(p));
    return a;
}
__device__ __forceinline__ void cpa16(uint32_t s, const void* g) {
    asm volatile("cp.async.cg.shared.global [%0], [%1], 16;" :: "r"(s), "l"(g));
}
#define CP_COMMIT() asm volatile("cp.async.commit_group;" ::: "memory")
#define CP_WAIT0()  asm volatile("cp.async.wait_group 0;"  ::: "memory")

__device__ __forceinline__ void mma16816(float* d, const uint32_t* a, const uint32_t* b) {
    asm volatile(
        "mma.sync.aligned.m16n8k16.row.col.f32.f16.f16.f32 "
        "{%0,%1,%2,%3}, {%4,%5,%6,%7}, {%8,%9}, {%0,%1,%2,%3};"
        : "+f"(d[0]), "+f"(d[1]), "+f"(d[2]), "+f"(d[3])
        : "r"(a[0]), "r"(a[1]), "r"(a[2]), "r"(a[3]), "r"(b[0]), "r"(b[1]));
}

// ---------------- smem geometry ---------------------------------------------
// A tiles / B-NT tiles: 128 rows x 64 fp16 (128B rows); swizzle c(0..7) ^= r&7
// B-NN tile:            64 rows x 128 fp16 (256B rows); swizzle c(0..15) ^= r&7
#define OFF_AH 0u
#define OFF_AL 16384u
#define OFF_BH 32768u
#define STAGE  49152u
#define SMEM_DYN (2 * STAGE)

__device__ __forceinline__ uint32_t swzA(int r, int c) {
    return (uint32_t)(r * 128 + ((c ^ (r & 7)) << 4));
}
__device__ __forceinline__ uint32_t swzB(int r, int c) {
    return (uint32_t)(r * 256 + ((c ^ (r & 7)) << 4));
}

template<bool NT>
__device__ __forceinline__ void load_stage(
    uint32_t sb, const __half* __restrict__ Ah, const __half* __restrict__ Al,
    const __half* __restrict__ Bh,
    int ldA, int ldB, int m0, int n0, int k0, int t)
{
    #pragma unroll
    for (int i = 0; i < 4; i++) {
        int u = t + (i << 8);
        int r = u >> 3, c = u & 7;
        uint32_t so = swzA(r, c);
        size_t go = (size_t)(m0 + r) * ldA + k0 + c * 8;
        cpa16(sb + OFF_AH + so, Ah + go);
        cpa16(sb + OFF_AL + so, Al + go);
    }
    if (NT) {
        #pragma unroll
        for (int i = 0; i < 4; i++) {
            int u = t + (i << 8);
            int r = u >> 3, c = u & 7;
            cpa16(sb + OFF_BH + swzA(r, c), Bh + (size_t)(n0 + r) * ldB + k0 + c * 8);
        }
    } else {
        #pragma unroll
        for (int i = 0; i < 4; i++) {
            int u = t + (i << 8);
            int r = u >> 4, c = u & 15;
            cpa16(sb + OFF_BH + swzB(r, c), Bh + (size_t)(k0 + r) * ldB + n0 + c * 8);
        }
    }
}

__device__ __forceinline__ void lds_a(uint32_t base, int wm, int lane, uint32_t af[4][4][4]) {
    #pragma unroll
    for (int k2 = 0; k2 < 4; k2++)
        #pragma unroll
        for (int mi = 0; mi < 4; mi++) {
            int row = wm * 64 + mi * 16 + (lane & 15);
            int c   = k2 * 2 + (lane >> 4);
            uint32_t a = base + swzA(row, c);
            asm volatile("ldmatrix.sync.aligned.m8n8.x4.shared.b16 {%0,%1,%2,%3}, [%4];"
                : "=r"(af[k2][mi][0]), "=r"(af[k2][mi][1]),
                  "=r"(af[k2][mi][2]), "=r"(af[k2][mi][3]) : "r"(a));
        }
}

template<bool NT>
__device__ __forceinline__ void lds_b(uint32_t base, int wn, int lane, uint32_t bfr[4][4][2]) {
    #pragma unroll
    for (int k2 = 0; k2 < 4; k2++)
        #pragma unroll
        for (int nb = 0; nb < 4; nb++) {
            if (NT) {
                int row = wn * 32 + nb * 8 + (lane & 7);
                int c   = k2 * 2 + ((lane >> 3) & 1);
                uint32_t a = base + swzA(row, c);
                asm volatile("ldmatrix.sync.aligned.m8n8.x2.shared.b16 {%0,%1}, [%2];"
                    : "=r"(bfr[k2][nb][0]), "=r"(bfr[k2][nb][1]) : "r"(a));
            } else {
                int row = k2 * 16 + (lane & 15);
                int c   = wn * 4 + nb;
                uint32_t a = base + swzB(row, c);
                asm volatile("ldmatrix.sync.aligned.m8n8.x2.trans.shared.b16 {%0,%1}, [%2];"
                    : "=r"(bfr[k2][nb][0]), "=r"(bfr[k2][nb][1]) : "r"(a));
            }
        }
}

// ---------------------------------------------------------------------------
// 2-pass fp16 GEMM:  D = alpha * (Ah + Al) @ B'   (B' = Bh, fp16)
//   NT=true : B given as [N][K] row-major.  NT=false: [K][N] row-major.
//   MODE 0: fp32*alpha out.  MODE 1: fp16 hi/lo out.  MODE 2: fp16 hi out.
// CTA 128x128, 8 warps (2x4), warp 64x32, K-chunk 64, 2-stage cp.async pipe.
// ---------------------------------------------------------------------------
template<bool NT, int MODE>
__global__ __launch_bounds__(256, 1) void gemm_mma(
    const __half* __restrict__ Ah, const __half* __restrict__ Al,
    const __half* __restrict__ Bh,
    float* __restrict__ Cf, __half* __restrict__ Ch, __half* __restrict__ Cl,
    int ldA, int ldB, int ldC, int K,
    size_t sA_, size_t sB_, size_t sC_, float alpha)
{
    extern __shared__ char sm[];
    uint32_t sb = smem_u32(sm);

    const int t    = threadIdx.x;
    const int warp = t >> 5;
    const int lane = t & 31;
    const int wm   = warp >> 2;
    const int wn   = warp & 3;

    const size_t z = blockIdx.z;
    Ah += z * sA_; Al += z * sA_; Bh += z * sB_;
    const int m0 = blockIdx.y * 128;
    const int n0 = blockIdx.x * 128;

    float acc[4][4][4] = {};
    const int nk = K >> 6;

    load_stage<NT>(sb, Ah, Al, Bh, ldA, ldB, m0, n0, 0, t);
    CP_COMMIT();

    uint32_t af[4][4][4];
    uint32_t bfr[4][4][2];

    for (int c = 0; c < nk; c++) {
        CP_WAIT0();
        __syncthreads();
        if (c + 1 < nk) {
            load_stage<NT>(sb + ((c + 1) & 1) * STAGE, Ah, Al, Bh,
                           ldA, ldB, m0, n0, (c + 1) << 6, t);
            CP_COMMIT();
        }
        uint32_t st = sb + (c & 1) * STAGE;

        lds_b<NT>(st + OFF_BH, wn, lane, bfr);

        // pass 1: Ah * B
        lds_a(st + OFF_AH, wm, lane, af);
        #pragma unroll
        for (int k2 = 0; k2 < 4; k2++)
            #pragma unroll
            for (int mi = 0; mi < 4; mi++)
                #pragma unroll
                for (int ni = 0; ni < 4; ni++)
                    mma16816(acc[mi][ni], af[k2][mi], bfr[k2][ni]);

        // pass 2: Al * B (reuse B frags)
        lds_a(st + OFF_AL, wm, lane, af);
        #pragma unroll
        for (int k2 = 0; k2 < 4; k2++)
            #pragma unroll
            for (int mi = 0; mi < 4; mi++)
                #pragma unroll
                for (int ni = 0; ni < 4; ni++)
                    mma16816(acc[mi][ni], af[k2][mi], bfr[k2][ni]);
    }

    // ---- epilogue ----
    const int g   = lane >> 2;
    const int tig = lane & 3;
    #pragma unroll
    for (int mi = 0; mi < 4; mi++) {
        #pragma unroll
        for (int ni = 0; ni < 4; ni++) {
            int row = m0 + wm * 64 + mi * 16 + g;
            int col = n0 + wn * 32 + ni * 8 + tig * 2;
            if (MODE == 0) {
                float* C = Cf + z * sC_;
                *(float2*)&C[(size_t)row * ldC + col] =
                    make_float2(acc[mi][ni][0] * alpha, acc[mi][ni][1] * alpha);
                *(float2*)&C[(size_t)(row + 8) * ldC + col] =
                    make_float2(acc[mi][ni][2] * alpha, acc[mi][ni][3] * alpha);
            } else {
                __half* H = Ch + z * sC_;
                #pragma unroll
                for (int rr = 0; rr < 2; rr++) {
                    float v0 = acc[mi][ni][rr * 2 + 0];
                    float v1 = acc[mi][ni][rr * 2 + 1];
                    __half h0 = __float2half(v0);
                    __half h1 = __float2half(v1);
                    size_t o = (size_t)(row + rr * 8) * ldC + col;
                    *(__half2*)&H[o] = __half2(h0, h1);
                    if (MODE == 1) {
                        __half* L = Cl + z * sC_;
                        *(__half2*)&L[o] = __half2(
                            __float2half(v0 - __half2float(h0)),
                            __float2half(v1 - __half2float(h1)));
                    }
                }
            }
        }
    }
}

// ---------------------------------------------------------------------------
// x -> fp16 hi/lo split, fused with sigma = |x @ W_sigma|.  One block per row.
// ---------------------------------------------------------------------------
__global__ __launch_bounds__(256) void xsplit_sigma(
    const float* __restrict__ x, const float* __restrict__ Wsig,
    __half* __restrict__ xh, __half* __restrict__ xl, float* __restrict__ sig)
{
    int row = blockIdx.x;
    int t   = threadIdx.x;
    size_t o = (size_t)row * CC + t;
    float v = x[o];
    __half h = __float2half(v);
    xh[o] = h;
    xl[o] = __float2half(v - __half2float(h));

    float p = v * Wsig[t];
    #pragma unroll
    for (int off = 16; off > 0; off >>= 1) p += __shfl_down_sync(0xFFFFFFFFu, p, off);
    __shared__ float wred[8];
    if ((t & 31) == 0) wred[t >> 5] = p;
    __syncthreads();
    if (t == 0) {
        float s = 0.f;
        #pragma unroll
        for (int w = 0; w < 8; w++) s += wred[w];
        sig[row] = fabsf(s);
    }
}

// W fp32 -> fp16
__global__ void wconv(const float* __restrict__ W, __half* __restrict__ Wf, int n)
{
    int i = blockIdx.x * blockDim.x + threadIdx.x;
    if (i < n) Wf[i] = __float2half(W[i]);
}

// ---------------------------------------------------------------------------
// batch softmax in place on S (fp32), plus fp16 hi/lo copies for SV GEMM
// ---------------------------------------------------------------------------
__global__ void softmax_batch_split(float* __restrict__ S,
                                    __half* __restrict__ Sh, __half* __restrict__ Sl)
{
    size_t idx = (size_t)blockIdx.x * blockDim.x + threadIdx.x;  // < N*N
    float v[BB];
    float m = -3.0e38f;
    #pragma unroll
    for (int b = 0; b < BB; b++) {
        v[b] = S[(size_t)b * N2 + idx];
        m = fmaxf(m, v[b]);
    }
    float s = 0.f;
    #pragma unroll
    for (int b = 0; b < BB; b++) { v[b] = __expf(v[b] - m); s += v[b]; }
    float inv = 1.0f / s;
    #pragma unroll
    for (int b = 0; b < BB; b++) {
        float w = v[b] * inv;
        size_t o = (size_t)b * N2 + idx;
        S[o] = w;
        __half h = __float2half(w);
        Sh[o] = h;
        Sl[o] = __float2half(w - __half2float(h));
    }
}

// ---------------------------------------------------------------------------
// P[b,i,j] = (|i-j| + sigma[b,i] * eps[b,i,j]) / row_sum
// ---------------------------------------------------------------------------
__global__ __launch_bounds__(256) void p_kernel(const float* __restrict__ eps,
                                                const float* __restrict__ sig,
                                                float* __restrict__ P)
{
    int row = blockIdx.x;
    int i   = row & (NN_ - 1);
    float sg = sig[row];
    const float* e = eps + (size_t)row * NN_;
    float* p = P + (size_t)row * NN_;

    float gv[4];
    float partial = 0.f;
    #pragma unroll
    for (int k = 0; k < 4; k++) {
        int j = threadIdx.x + k * 256;
        gv[k] = fabsf((float)(i - j)) + sg * e[j];
        partial += gv[k];
    }
    __shared__ float red[256];
    red[threadIdx.x] = partial;
    __syncthreads();
    #pragma unroll
    for (int o = 128; o > 0; o >>= 1) {
        if (threadIdx.x < o) red[threadIdx.x] += red[threadIdx.x + o];
        __syncthreads();
    }
    float inv = 1.0f / red[0];
    #pragma unroll
    for (int k = 0; k < 4; k++)
        p[threadIdx.x + k * 256] = gv[k] * inv;
}

// ---------------------------------------------------------------------------
extern "C" void kernel_launch(void* const* d_in, const int* in_sizes, int n_in,
                              void* d_out, int out_size)
{
    const float* x     = (const float*)d_in[0];
    const float* W_q   = (const float*)d_in[1];
    const float* W_k   = (const float*)d_in[2];
    const float* W_v   = (const float*)d_in[3];
    const float* W_sig = (const float*)d_in[4];
    const float* eps   = (const float*)d_in[5];

    float* out = (float*)d_out;
    float* Z = out;
    float* P = out + BNC;
    float* S = out + BNC + BNN;

    #define SYM(T, v, s) T* v; { void* _p; cudaGetSymbolAddress(&_p, s); v = (T*)_p; }
    SYM(__half, xh, g_xh)  SYM(__half, xl, g_xl)
    SYM(__half, Wf, g_W)
    SYM(__half, Qh, g_Qh)  SYM(__half, Ql, g_Ql)
    SYM(__half, Kh, g_Kh)
    SYM(__half, Vh, g_Vh)
    SYM(__half, Sh, g_Sh)  SYM(__half, Sl, g_Sl)
    SYM(float,  sg, g_sig)
    #undef SYM

    cudaFuncSetAttribute(gemm_mma<false, 1>, cudaFuncAttributeMaxDynamicSharedMemorySize, SMEM_DYN);
    cudaFuncSetAttribute(gemm_mma<false, 2>, cudaFuncAttributeMaxDynamicSharedMemorySize, SMEM_DYN);
    cudaFuncSetAttribute(gemm_mma<true,  0>, cudaFuncAttributeMaxDynamicSharedMemorySize, SMEM_DYN);
    cudaFuncSetAttribute(gemm_mma<false, 0>, cudaFuncAttributeMaxDynamicSharedMemorySize, SMEM_DYN);

    // 1) split x (+ fused sigma) and convert weights
    xsplit_sigma<<<BB * NN_, 256>>>(x, W_sig, xh, xl, sg);
    wconv<<<CC * CC / 256, 256>>>(W_q, Wf + 0 * CC * CC, CC * CC);
    wconv<<<CC * CC / 256, 256>>>(W_k, Wf + 1 * CC * CC, CC * CC);
    wconv<<<CC * CC / 256, 256>>>(W_v, Wf + 2 * CC * CC, CC * CC);

    // 2) projections: Q (hi/lo: feeds A side of scores), K,V (hi only: B sides)
    {
        dim3 grid(CC / 128, (BB * NN_) / 128, 1);
        gemm_mma<false, 1><<<grid, 256, SMEM_DYN>>>(
            xh, xl, Wf + 0 * CC * CC, nullptr, Qh, Ql, CC, CC, CC, CC, 0, 0, 0, 1.f);
        gemm_mma<false, 2><<<grid, 256, SMEM_DYN>>>(
            xh, xl, Wf + 1 * CC * CC, nullptr, Kh, nullptr, CC, CC, CC, CC, 0, 0, 0, 1.f);
        gemm_mma<false, 2><<<grid, 256, SMEM_DYN>>>(
            xh, xl, Wf + 2 * CC * CC, nullptr, Vh, nullptr, CC, CC, CC, CC, 0, 0, 0, 1.f);
    }

    // 3) scores = Q K^T / 16 into S region (NT)
    {
        dim3 grid(NN_ / 128, NN_ / 128, BB);
        gemm_mma<true, 0><<<grid, 256, SMEM_DYN>>>(
            Qh, Ql, Kh, S, nullptr, nullptr,
            CC, CC, NN_, CC, (size_t)NC, (size_t)NC, (size_t)N2, 0.0625f);
    }

    // 4) batch softmax in place + fp16 split of S
    softmax_batch_split<<<N2 / 256, 256>>>(S, Sh, Sl);

    // 5) prior association P
    p_kernel<<<BB * NN_, 256>>>(eps, sg, P);

    // 6) Z = S @ V  (NN)
    {
        dim3 grid(CC / 128, NN_ / 128, BB);
        gemm_mma<false, 0><<<grid, 256, SMEM_DYN>>>(
            Sh, Sl, Vh, Z, nullptr, nullptr,
            NN_, CC, CC, NN_, (size_t)N2, (size_t)NC, (size_t)NC, 1.f);
    }
}

// round 11
// speedup vs baseline: 4.0523x; 1.2472x over previous
#include <cuda_runtime.h>
#include <cuda_fp16.h>
#include <cstdint>
#include <math.h>

#define BB   16
#define NN_  1024
#define CC   256
#define BNC  (BB * NN_ * CC)      // 4,194,304
#define BNN  (BB * NN_ * NN_)     // 16,777,216
#define NC   (NN_ * CC)           // 262,144
#define N2   (NN_ * NN_)          // 1,048,576

// ---------------- scratch (__device__ globals: allocation-free) -------------
__device__ __align__(16) __half g_xh[BNC], g_xl[BNC];
__device__ __align__(16) __half g_W[3][CC * CC];
__device__ __align__(16) __half g_Qh[BNC];
__device__ __align__(16) __half g_Kh[BNC];
__device__ __align__(16) __half g_Vh[BNC];
__device__ __align__(16) __half g_Sh[BNN];
__device__ float g_sig[BB * NN_];

// ---------------- base-target PTX helpers -----------------------------------
__device__ __forceinline__ uint32_t smem_u32(const void* p) {
    uint32_t a;
    asm("{ .reg .u64 t; cvta.to.shared.u64 t, %1; cvt.u32.u64 %0, t; }" : "=r"(a) : "l"(p));
    return a;
}
__device__ __forceinline__ void cpa16(uint32_t s, const void* g) {
    asm volatile("cp.async.cg.shared.global [%0], [%1], 16;" :: "r"(s), "l"(g));
}
#define CP_COMMIT() asm volatile("cp.async.commit_group;" ::: "memory")
#define CP_WAIT0()  asm volatile("cp.async.wait_group 0;"  ::: "memory")

__device__ __forceinline__ void mma16816(float* d, const uint32_t* a, const uint32_t* b) {
    asm volatile(
        "mma.sync.aligned.m16n8k16.row.col.f32.f16.f16.f32 "
        "{%0,%1,%2,%3}, {%4,%5,%6,%7}, {%8,%9}, {%0,%1,%2,%3};"
        : "+f"(d[0]), "+f"(d[1]), "+f"(d[2]), "+f"(d[3])
        : "r"(a[0]), "r"(a[1]), "r"(a[2]), "r"(a[3]), "r"(b[0]), "r"(b[1]));
}

// ---------------- smem geometry ---------------------------------------------
// A tiles / B-NT tiles: 128 rows x 64 fp16 (128B rows); swizzle c(0..7) ^= r&7
// B-NN tile:            64 rows x 128 fp16 (256B rows); swizzle c(0..15) ^= r&7
__device__ __forceinline__ uint32_t swzA(int r, int c) {
    return (uint32_t)(r * 128 + ((c ^ (r & 7)) << 4));
}
__device__ __forceinline__ uint32_t swzB(int r, int c) {
    return (uint32_t)(r * 256 + ((c ^ (r & 7)) << 4));
}

template<bool NT, bool TWOPASS>
__device__ __forceinline__ void load_stage(
    uint32_t sb, const __half* __restrict__ Ah, const __half* __restrict__ Al,
    const __half* __restrict__ Bh,
    int ldA, int ldB, int m0, int n0, int k0, int t)
{
    const uint32_t offB = TWOPASS ? 32768u : 16384u;
    #pragma unroll
    for (int i = 0; i < 4; i++) {
        int u = t + (i << 8);
        int r = u >> 3, c = u & 7;
        uint32_t so = swzA(r, c);
        size_t go = (size_t)(m0 + r) * ldA + k0 + c * 8;
        cpa16(sb + so, Ah + go);
        if (TWOPASS) cpa16(sb + 16384u + so, Al + go);
    }
    if (NT) {
        #pragma unroll
        for (int i = 0; i < 4; i++) {
            int u = t + (i << 8);
            int r = u >> 3, c = u & 7;
            cpa16(sb + offB + swzA(r, c), Bh + (size_t)(n0 + r) * ldB + k0 + c * 8);
        }
    } else {
        #pragma unroll
        for (int i = 0; i < 4; i++) {
            int u = t + (i << 8);
            int r = u >> 4, c = u & 15;
            cpa16(sb + offB + swzB(r, c), Bh + (size_t)(k0 + r) * ldB + n0 + c * 8);
        }
    }
}

__device__ __forceinline__ void lds_a(uint32_t base, int wm, int lane, uint32_t af[4][4][4]) {
    #pragma unroll
    for (int k2 = 0; k2 < 4; k2++)
        #pragma unroll
        for (int mi = 0; mi < 4; mi++) {
            int row = wm * 64 + mi * 16 + (lane & 15);
            int c   = k2 * 2 + (lane >> 4);
            uint32_t a = base + swzA(row, c);
            asm volatile("ldmatrix.sync.aligned.m8n8.x4.shared.b16 {%0,%1,%2,%3}, [%4];"
                : "=r"(af[k2][mi][0]), "=r"(af[k2][mi][1]),
                  "=r"(af[k2][mi][2]), "=r"(af[k2][mi][3]) : "r"(a));
        }
}

template<bool NT>
__device__ __forceinline__ void lds_b(uint32_t base, int wn, int lane, uint32_t bfr[4][4][2]) {
    #pragma unroll
    for (int k2 = 0; k2 < 4; k2++)
        #pragma unroll
        for (int nb = 0; nb < 4; nb++) {
            if (NT) {
                int row = wn * 32 + nb * 8 + (lane & 7);
                int c   = k2 * 2 + ((lane >> 3) & 1);
                uint32_t a = base + swzA(row, c);
                asm volatile("ldmatrix.sync.aligned.m8n8.x2.shared.b16 {%0,%1}, [%2];"
                    : "=r"(bfr[k2][nb][0]), "=r"(bfr[k2][nb][1]) : "r"(a));
            } else {
                int row = k2 * 16 + (lane & 15);
                int c   = wn * 4 + nb;
                uint32_t a = base + swzB(row, c);
                asm volatile("ldmatrix.sync.aligned.m8n8.x2.trans.shared.b16 {%0,%1}, [%2];"
                    : "=r"(bfr[k2][nb][0]), "=r"(bfr[k2][nb][1]) : "r"(a));
            }
        }
}

// ---------------------------------------------------------------------------
// fp16 GEMM:  D = alpha * A @ B'    A = Ah (+ Al if TWOPASS), fp32 accum
//   NT=true : B given as [N][K] row-major.  NT=false: [K][N] row-major.
//   MODE 0: fp32*alpha out.  MODE 2: fp16 out.
// CTA 128x128, 8 warps (2x4), warp 64x32, K-chunk 64, 2-stage cp.async pipe.
// ---------------------------------------------------------------------------
template<bool NT, int MODE, bool TWOPASS>
__global__ __launch_bounds__(256, 1) void gemm_mma(
    const __half* __restrict__ Ah, const __half* __restrict__ Al,
    const __half* __restrict__ Bh,
    float* __restrict__ Cf, __half* __restrict__ Ch,
    int ldA, int ldB, int ldC, int K,
    size_t sA_, size_t sB_, size_t sC_, float alpha)
{
    extern __shared__ char sm[];
    uint32_t sb = smem_u32(sm);
    const uint32_t offB  = TWOPASS ? 32768u : 16384u;
    const uint32_t STAGE = TWOPASS ? 49152u : 32768u;

    const int t    = threadIdx.x;
    const int warp = t >> 5;
    const int lane = t & 31;
    const int wm   = warp >> 2;
    const int wn   = warp & 3;

    const size_t z = blockIdx.z;
    Ah += z * sA_; if (TWOPASS) Al += z * sA_; Bh += z * sB_;
    const int m0 = blockIdx.y * 128;
    const int n0 = blockIdx.x * 128;

    float acc[4][4][4] = {};
    const int nk = K >> 6;

    load_stage<NT, TWOPASS>(sb, Ah, Al, Bh, ldA, ldB, m0, n0, 0, t);
    CP_COMMIT();

    uint32_t af[4][4][4];
    uint32_t bfr[4][4][2];

    for (int c = 0; c < nk; c++) {
        CP_WAIT0();
        __syncthreads();
        if (c + 1 < nk) {
            load_stage<NT, TWOPASS>(sb + ((c + 1) & 1) * STAGE, Ah, Al, Bh,
                                    ldA, ldB, m0, n0, (c + 1) << 6, t);
            CP_COMMIT();
        }
        uint32_t st = sb + (c & 1) * STAGE;

        lds_b<NT>(st + offB, wn, lane, bfr);

        // pass 1: Ah * B
        lds_a(st, wm, lane, af);
        #pragma unroll
        for (int k2 = 0; k2 < 4; k2++)
            #pragma unroll
            for (int mi = 0; mi < 4; mi++)
                #pragma unroll
                for (int ni = 0; ni < 4; ni++)
                    mma16816(acc[mi][ni], af[k2][mi], bfr[k2][ni]);

        // pass 2: Al * B (reuse B frags)
        if (TWOPASS) {
            lds_a(st + 16384u, wm, lane, af);
            #pragma unroll
            for (int k2 = 0; k2 < 4; k2++)
                #pragma unroll
                for (int mi = 0; mi < 4; mi++)
                    #pragma unroll
                    for (int ni = 0; ni < 4; ni++)
                        mma16816(acc[mi][ni], af[k2][mi], bfr[k2][ni]);
        }
    }

    // ---- epilogue ----
    const int g   = lane >> 2;
    const int tig = lane & 3;
    #pragma unroll
    for (int mi = 0; mi < 4; mi++) {
        #pragma unroll
        for (int ni = 0; ni < 4; ni++) {
            int row = m0 + wm * 64 + mi * 16 + g;
            int col = n0 + wn * 32 + ni * 8 + tig * 2;
            if (MODE == 0) {
                float* C = Cf + z * sC_;
                *(float2*)&C[(size_t)row * ldC + col] =
                    make_float2(acc[mi][ni][0] * alpha, acc[mi][ni][1] * alpha);
                *(float2*)&C[(size_t)(row + 8) * ldC + col] =
                    make_float2(acc[mi][ni][2] * alpha, acc[mi][ni][3] * alpha);
            } else {
                __half* H = Ch + z * sC_;
                #pragma unroll
                for (int rr = 0; rr < 2; rr++) {
                    size_t o = (size_t)(row + rr * 8) * ldC + col;
                    *(__half2*)&H[o] = __half2(
                        __float2half(acc[mi][ni][rr * 2 + 0]),
                        __float2half(acc[mi][ni][rr * 2 + 1]));
                }
            }
        }
    }
}

// ---------------------------------------------------------------------------
// x -> fp16 hi/lo split, fused with sigma = |x @ W_sigma|.  One block per row.
// ---------------------------------------------------------------------------
__global__ __launch_bounds__(256) void xsplit_sigma(
    const float* __restrict__ x, const float* __restrict__ Wsig,
    __half* __restrict__ xh, __half* __restrict__ xl, float* __restrict__ sig)
{
    int row = blockIdx.x;
    int t   = threadIdx.x;
    size_t o = (size_t)row * CC + t;
    float v = x[o];
    __half h = __float2half(v);
    xh[o] = h;
    xl[o] = __float2half(v - __half2float(h));

    float p = v * Wsig[t];
    #pragma unroll
    for (int off = 16; off > 0; off >>= 1) p += __shfl_down_sync(0xFFFFFFFFu, p, off);
    __shared__ float wred[8];
    if ((t & 31) == 0) wred[t >> 5] = p;
    __syncthreads();
    if (t == 0) {
        float s = 0.f;
        #pragma unroll
        for (int w = 0; w < 8; w++) s += wred[w];
        sig[row] = fabsf(s);
    }
}

// all three W fp32 -> fp16 in one launch
__global__ void wconv(const float* __restrict__ W0, const float* __restrict__ W1,
                      const float* __restrict__ W2, __half* __restrict__ Wf)
{
    int i = blockIdx.x * blockDim.x + threadIdx.x;   // < 3*CC*CC
    int which = i >> 16, j = i & 65535;
    const float* src = which == 0 ? W0 : (which == 1 ? W1 : W2);
    Wf[i] = __float2half(src[j]);
}

// ---------------------------------------------------------------------------
// batch softmax in place on S (fp32), plus fp16 copy for SV GEMM
// ---------------------------------------------------------------------------
__global__ void softmax_batch_split(float* __restrict__ S, __half* __restrict__ Sh)
{
    size_t idx = (size_t)blockIdx.x * blockDim.x + threadIdx.x;  // < N*N
    float v[BB];
    float m = -3.0e38f;
    #pragma unroll
    for (int b = 0; b < BB; b++) {
        v[b] = S[(size_t)b * N2 + idx];
        m = fmaxf(m, v[b]);
    }
    float s = 0.f;
    #pragma unroll
    for (int b = 0; b < BB; b++) { v[b] = __expf(v[b] - m); s += v[b]; }
    float inv = 1.0f / s;
    #pragma unroll
    for (int b = 0; b < BB; b++) {
        float w = v[b] * inv;
        size_t o = (size_t)b * N2 + idx;
        S[o] = w;
        Sh[o] = __float2half(w);
    }
}

// ---------------------------------------------------------------------------
// P[b,i,j] = (|i-j| + sigma[b,i] * eps[b,i,j]) / row_sum
// ---------------------------------------------------------------------------
__global__ __launch_bounds__(256) void p_kernel(const float* __restrict__ eps,
                                                const float* __restrict__ sig,
                                                float* __restrict__ P)
{
    int row = blockIdx.x;
    int i   = row & (NN_ - 1);
    float sg = sig[row];
    const float* e = eps + (size_t)row * NN_;
    float* p = P + (size_t)row * NN_;

    float gv[4];
    float partial = 0.f;
    #pragma unroll
    for (int k = 0; k < 4; k++) {
        int j = threadIdx.x + k * 256;
        gv[k] = fabsf((float)(i - j)) + sg * e[j];
        partial += gv[k];
    }
    __shared__ float red[256];
    red[threadIdx.x] = partial;
    __syncthreads();
    #pragma unroll
    for (int o = 128; o > 0; o >>= 1) {
        if (threadIdx.x < o) red[threadIdx.x] += red[threadIdx.x + o];
        __syncthreads();
    }
    float inv = 1.0f / red[0];
    #pragma unroll
    for (int k = 0; k < 4; k++)
        p[threadIdx.x + k * 256] = gv[k] * inv;
}

// ---------------------------------------------------------------------------
extern "C" void kernel_launch(void* const* d_in, const int* in_sizes, int n_in,
                              void* d_out, int out_size)
{
    const float* x     = (const float*)d_in[0];
    const float* W_q   = (const float*)d_in[1];
    const float* W_k   = (const float*)d_in[2];
    const float* W_v   = (const float*)d_in[3];
    const float* W_sig = (const float*)d_in[4];
    const float* eps   = (const float*)d_in[5];

    float* out = (float*)d_out;
    float* Z = out;
    float* P = out + BNC;
    float* S = out + BNC + BNN;

    #define SYM(T, v, s) T* v; { void* _p; cudaGetSymbolAddress(&_p, s); v = (T*)_p; }
    SYM(__half, xh, g_xh)  SYM(__half, xl, g_xl)
    SYM(__half, Wf, g_W)
    SYM(__half, Qh, g_Qh)
    SYM(__half, Kh, g_Kh)
    SYM(__half, Vh, g_Vh)
    SYM(__half, Sh, g_Sh)
    SYM(float,  sg, g_sig)
    #undef SYM

    const int SM_2P = 2 * 49152;
    const int SM_1P = 2 * 32768;
    cudaFuncSetAttribute((const void*)gemm_mma<false, 2, true >, cudaFuncAttributeMaxDynamicSharedMemorySize, SM_2P);
    cudaFuncSetAttribute((const void*)gemm_mma<true,  0, false>, cudaFuncAttributeMaxDynamicSharedMemorySize, SM_1P);
    cudaFuncSetAttribute((const void*)gemm_mma<false, 0, false>, cudaFuncAttributeMaxDynamicSharedMemorySize, SM_1P);

    // 1) split x (+ fused sigma), convert all weights in one launch
    xsplit_sigma<<<BB * NN_, 256>>>(x, W_sig, xh, xl, sg);
    wconv<<<3 * CC * CC / 256, 256>>>(W_q, W_k, W_v, Wf);

    // 2) projections: 2-pass (x hi/lo), fp16 outputs
    {
        dim3 grid(CC / 128, (BB * NN_) / 128, 1);
        gemm_mma<false, 2, true><<<grid, 256, SM_2P>>>(
            xh, xl, Wf + 0 * CC * CC, nullptr, Qh, CC, CC, CC, CC, 0, 0, 0, 1.f);
        gemm_mma<false, 2, true><<<grid, 256, SM_2P>>>(
            xh, xl, Wf + 1 * CC * CC, nullptr, Kh, CC, CC, CC, CC, 0, 0, 0, 1.f);
        gemm_mma<false, 2, true><<<grid, 256, SM_2P>>>(
            xh, xl, Wf + 2 * CC * CC, nullptr, Vh, CC, CC, CC, CC, 0, 0, 0, 1.f);
    }

    // 3) scores = Qh Kh^T / 16 into S region (NT, single-pass)
    {
        dim3 grid(NN_ / 128, NN_ / 128, BB);
        gemm_mma<true, 0, false><<<grid, 256, SM_1P>>>(
            Qh, nullptr, Kh, S, nullptr,
            CC, CC, NN_, CC, (size_t)NC, (size_t)NC, (size_t)N2, 0.0625f);
    }

    // 4) batch softmax in place + fp16 copy of S
    softmax_batch_split<<<N2 / 256, 256>>>(S, Sh);

    // 5) prior association P
    p_kernel<<<BB * NN_, 256>>>(eps, sg, P);

    // 6) Z = Sh @ Vh  (NN, single-pass)
    {
        dim3 grid(CC / 128, NN_ / 128, BB);
        gemm_mma<false, 0, false><<<grid, 256, SM_1P>>>(
            Sh, nullptr, Vh, Z, nullptr,
            NN_, CC, CC, NN_, (size_t)N2, (size_t)NC, (size_t)NC, 1.f);
    }
}